// round 5
// baseline (speedup 1.0000x reference)
#include <cuda_runtime.h>
#include <cuda_bf16.h>

#define BB     32
#define NN     1024
#define DD     128
#define C_OUT  16
#define PP     16      // P*P
#define OUTW   128     // Hg * P

// Fused single kernel. Block = (b, gh): 1024 blocks x 128 threads.
//   Phase 0: stage W (8 KB) + this block's 32 x-rows (16 KB) into smem, coalesced.
//   Phase 1: thread (row=t>>2, pg=t&3) computes xw[row, pg*4..pg*4+3]
//            (dots vs sW, quad-broadcast reads). Also builds
//            sCBM[c][p] = (emb[c]·W[p] + bias[p]) * mask[b,c].
//   Phase 2: thread (lane=gw=t&31, cg=t>>5) writes 16 float4 rows:
//            out[b,c, gh*4+ph, gw*4+pw] = xw[gw, ph*4+pw]*mask[b,c] + sCBM[c][ph*4+pw]
__global__ __launch_bounds__(128)
void qbd_fused(const float* __restrict__ x,
               const float* __restrict__ mask,
               const float* __restrict__ emb,
               const float* __restrict__ W,
               const float* __restrict__ bias,
               float* __restrict__ out)
{
    __shared__ __align__(16) float4 sW[PP * 33];     // row stride 33 float4 (pad)
    __shared__ __align__(16) float4 sX[32 * 33];     // 32 rows x 32 float4, stride 33
    __shared__ __align__(16) float  sXW[32 * 20];    // stride 20: conflict-free float4 reads
    __shared__ __align__(16) float  sCBM[C_OUT * PP];
    __shared__ float sMask[C_OUT];

    const int t  = threadIdx.x;
    const int b  = blockIdx.x >> 5;
    const int gh = blockIdx.x & 31;

    // ---- phase 0: stage W and x, fully coalesced ----
    {
        const float4* Wv = (const float4*)W;
        #pragma unroll
        for (int i = 0; i < 4; i++) {
            const int g = t + 128 * i;               // 0..511
            sW[(g >> 5) * 33 + (g & 31)] = Wv[g];
        }
        const float4* xv = (const float4*)(x + (size_t)(b * NN + gh * 32) * DD);
        #pragma unroll
        for (int i = 0; i < 8; i++) {
            const int g = t + 128 * i;               // 0..1023
            sX[(g >> 5) * 33 + (g & 31)] = __ldg(xv + g);
        }
        if (t < C_OUT) sMask[t] = __ldg(mask + b * C_OUT + t);
    }
    __syncthreads();

    // ---- phase 1a: dot products for this block's 32 tokens ----
    {
        const int row = t >> 2;                      // 0..31 (local token)
        const int pg  = t & 3;                       // patch group
        const float4* xr = &sX[row * 33];
        const float4* w0 = &sW[(pg * 4 + 0) * 33];
        const float4* w1 = &sW[(pg * 4 + 1) * 33];
        const float4* w2 = &sW[(pg * 4 + 2) * 33];
        const float4* w3 = &sW[(pg * 4 + 3) * 33];
        float4 acc = make_float4(0.f, 0.f, 0.f, 0.f);
        #pragma unroll
        for (int d4 = 0; d4 < DD / 4; d4++) {
            const float4 xv = xr[d4];
            const float4 a = w0[d4], bb2 = w1[d4], c = w2[d4], dd2 = w3[d4];
            acc.x = fmaf(xv.x, a.x,   fmaf(xv.y, a.y,   fmaf(xv.z, a.z,   fmaf(xv.w, a.w,   acc.x))));
            acc.y = fmaf(xv.x, bb2.x, fmaf(xv.y, bb2.y, fmaf(xv.z, bb2.z, fmaf(xv.w, bb2.w, acc.y))));
            acc.z = fmaf(xv.x, c.x,   fmaf(xv.y, c.y,   fmaf(xv.z, c.z,   fmaf(xv.w, c.w,   acc.z))));
            acc.w = fmaf(xv.x, dd2.x, fmaf(xv.y, dd2.y, fmaf(xv.z, dd2.z, fmaf(xv.w, dd2.w, acc.w))));
        }
        *(float4*)&sXW[row * 20 + pg * 4] = acc;     // 80B row stride, 16B aligned
    }

    // ---- phase 1b: channel table (emb[c]·W[p] + bias[p]) * mask[b,c] ----
    #pragma unroll
    for (int i = t; i < C_OUT * PP; i += 128) {
        const int c = i >> 4;
        const int p = i & 15;
        float s = __ldg(bias + p);
        const float4* e = (const float4*)(emb + c * DD);
        const float4* w = &sW[p * 33];
        #pragma unroll 8
        for (int d4 = 0; d4 < DD / 4; d4++) {
            const float4 ev = __ldg(e + d4);
            const float4 wv = w[d4];
            s = fmaf(ev.x, wv.x, fmaf(ev.y, wv.y, fmaf(ev.z, wv.z, fmaf(ev.w, wv.w, s))));
        }
        sCBM[i] = s * sMask[c];
    }
    __syncthreads();

    // ---- phase 2: epilogue, 512 B coalesced rows ----
    const int lane = t & 31;                         // gw
    const int cg   = t >> 5;                         // channel group [0,4)
    float4 xv0 = *(const float4*)&sXW[lane * 20 + 0];
    float4 xv1 = *(const float4*)&sXW[lane * 20 + 4];
    float4 xv2 = *(const float4*)&sXW[lane * 20 + 8];
    float4 xv3 = *(const float4*)&sXW[lane * 20 + 12];

    float4* outv = (float4*)out;
    #pragma unroll
    for (int j = 0; j < 4; j++) {
        const int c = cg * 4 + j;
        const float mk = sMask[c];
        const size_t base = ((size_t)(b * C_OUT + c) * OUTW + gh * 4) * (OUTW / 4) + lane;
        #pragma unroll
        for (int ph = 0; ph < 4; ph++) {
            const float4 xp  = (ph == 0) ? xv0 : (ph == 1) ? xv1 : (ph == 2) ? xv2 : xv3;
            const float4 cbv = *(const float4*)&sCBM[c * PP + ph * 4];  // broadcast
            float4 v;
            v.x = fmaf(xp.x, mk, cbv.x);
            v.y = fmaf(xp.y, mk, cbv.y);
            v.z = fmaf(xp.z, mk, cbv.z);
            v.w = fmaf(xp.w, mk, cbv.w);
            outv[base + (size_t)ph * (OUTW / 4)] = v;
        }
    }
}

extern "C" void kernel_launch(void* const* d_in, const int* in_sizes, int n_in,
                              void* d_out, int out_size)
{
    const float* x    = (const float*)d_in[0];   // (32,1024,128)
    const float* mask = (const float*)d_in[1];   // (32,16)
    const float* emb  = (const float*)d_in[2];   // (256,128)
    const float* W    = (const float*)d_in[3];   // (16,128)
    const float* bias = (const float*)d_in[4];   // (16,)
    float* out = (float*)d_out;                  // (32,16,128,128)

    qbd_fused<<<BB * 32, 128>>>(x, mask, emb, W, bias, out);
}